// round 10
// baseline (speedup 1.0000x reference)
#include <cuda_runtime.h>
#include <cuda_fp16.h>
#include <cstdint>

// Problem constants (fixed by the dataset)
#define NN_MAX 10000
#define EE_MAX 120000

// ---------------- scratch (device globals; no allocation allowed) ----------------
__device__ __half g_h2[(size_t)EE_MAX * 256];         // 61.4 MB (fp16)
__device__ __half g_we[(size_t)EE_MAX * 1024];        // 245.8 MB (fp16)
__device__ __half g_w2h[128 * 256];                   // k2_w fp16 [K,N]
__device__ __half g_w3h[256 * 1024];                  // k3_w fp16 [K,N]
__device__ float g_h[(size_t)NN_MAX * 32];
__device__ float g_aggr[(size_t)NN_MAX * 32];
__device__ float g_cnt[(size_t)NN_MAX];

// ---------------- mma / ldmatrix / cp.async helpers ----------------
__device__ __forceinline__ void mma_m16n8k16_f16(float* c, const uint32_t* a, const uint32_t* b) {
    asm volatile(
        "mma.sync.aligned.m16n8k16.row.col.f32.f16.f16.f32 "
        "{%0,%1,%2,%3}, {%4,%5,%6,%7}, {%8,%9}, {%0,%1,%2,%3};\n"
        : "+f"(c[0]), "+f"(c[1]), "+f"(c[2]), "+f"(c[3])
        : "r"(a[0]), "r"(a[1]), "r"(a[2]), "r"(a[3]), "r"(b[0]), "r"(b[1]));
}

__device__ __forceinline__ void ldmatrix_x4(uint32_t* r, const __half* smem_ptr) {
    uint32_t addr = (uint32_t)__cvta_generic_to_shared(smem_ptr);
    asm volatile("ldmatrix.sync.aligned.m8n8.x4.shared.b16 {%0,%1,%2,%3}, [%4];"
                 : "=r"(r[0]), "=r"(r[1]), "=r"(r[2]), "=r"(r[3]) : "r"(addr));
}

__device__ __forceinline__ void ldmatrix_x2_trans(uint32_t* r, const __half* smem_ptr) {
    uint32_t addr = (uint32_t)__cvta_generic_to_shared(smem_ptr);
    asm volatile("ldmatrix.sync.aligned.m8n8.x2.trans.shared.b16 {%0,%1}, [%2];"
                 : "=r"(r[0]), "=r"(r[1]) : "r"(addr));
}

__device__ __forceinline__ void cp_async16g(__half* smem_dst, const __half* gmem_src) {
    uint32_t s = (uint32_t)__cvta_generic_to_shared(smem_dst);
    asm volatile("cp.async.cg.shared.global [%0], [%1], 16;\n" :: "r"(s), "l"(gmem_src));
}
__device__ __forceinline__ void cp_async16p(__half* smem_dst, const __half* gmem_src, int src_bytes) {
    uint32_t s = (uint32_t)__cvta_generic_to_shared(smem_dst);
    asm volatile("cp.async.cg.shared.global [%0], [%1], 16, %2;\n"
                 :: "r"(s), "l"(gmem_src), "r"(src_bytes));
}
__device__ __forceinline__ void cp_commit() { asm volatile("cp.async.commit_group;\n"); }
__device__ __forceinline__ void cp_wait1() { asm volatile("cp.async.wait_group 1;\n"); }
__device__ __forceinline__ void cp_wait0() { asm volatile("cp.async.wait_group 0;\n"); }

// ---------------- fp16 tiled GEMM, BK=64, optional fused first-layer A ----------------
// C[M,N] = op( A[M,K] @ B[K,N] + bias ),  A fp16 (or computed from ea@k1w),
// B fp16 [K,N], C fp16. BM=128 fixed, BK=64, warps 2(m) x WN_(n), warp tile 64 x NT*8.
#define GK_SAS 72   // halves per A row (64 + 8 pad), 144B rows: conflict-free

template <bool RELU, bool FUSE_A, int WN_, int NT>
__global__ void __launch_bounds__(64 * WN_, 1)
gemm_f16_kernel(const __half* __restrict__ A,
                const float* __restrict__ ea, const float* __restrict__ k1w,
                const float* __restrict__ k1b,
                const __half* __restrict__ B, const float* __restrict__ bias,
                __half* __restrict__ C, int M, int N, int K) {
    constexpr int NTHR = 64 * WN_;
    constexpr int BN = WN_ * NT * 8;
    constexpr int SBS = BN + 8;
    extern __shared__ __half smemh[];
    __half* sA = smemh;                               // [2][128][GK_SAS]
    __half* sB = smemh + 2 * 128 * GK_SAS;            // [2][64][SBS]
    float* sEA  = (float*)(smemh + 2 * 128 * GK_SAS + 2 * 64 * SBS);  // [128][6]
    float* sK1W = sEA + 768;                          // [6][128]
    float* sK1B = sK1W + 768;                         // [128]

    const int tid = threadIdx.x;
    const int warp = tid >> 5;
    const int lane = tid & 31;
    const int wm = (warp / WN_) * 64;
    const int wn = (warp % WN_) * (NT * 8);
    const int m0 = blockIdx.y * 128;
    const int n0 = blockIdx.x * BN;

    if (FUSE_A) {
        int valid = (M - m0) * 6;
        if (valid > 768) valid = 768;
        for (int idx = tid; idx < 768; idx += NTHR)
            sEA[idx] = (idx < valid) ? ea[(size_t)m0 * 6 + idx] : 0.f;
        for (int idx = tid; idx < 768; idx += NTHR) sK1W[idx] = k1w[idx];
        for (int idx = tid; idx < 128; idx += NTHR) sK1B[idx] = k1b[idx];
        __syncthreads();
    }

    auto loadA = [&](int kt, int buf) {
#pragma unroll
        for (int i = 0; i < 1024 / NTHR; ++i) {
            int idx = i * NTHR + tid;
            int r = idx >> 3, seg = idx & 7;
            int gr = m0 + r;
            int grc = gr < M ? gr : (M - 1);
            cp_async16p(sA + buf * 128 * GK_SAS + r * GK_SAS + seg * 8,
                        A + (size_t)grc * K + kt * 64 + seg * 8, gr < M ? 16 : 0);
        }
    };
    auto computeA = [&](int kt, int buf) {
        __half* d = sA + buf * 128 * GK_SAS;
#pragma unroll
        for (int i = 0; i < 4096 / NTHR; ++i) {
            int idx = i * NTHR + tid;
            int r = idx >> 5, cp2 = idx & 31;
            int k0 = kt * 64 + cp2 * 2;
            float e0 = sEA[r * 6 + 0], e1 = sEA[r * 6 + 1], e2 = sEA[r * 6 + 2];
            float e3 = sEA[r * 6 + 3], e4 = sEA[r * 6 + 4], e5 = sEA[r * 6 + 5];
            float v0 = sK1B[k0] + e0 * sK1W[k0] + e1 * sK1W[128 + k0] + e2 * sK1W[256 + k0]
                     + e3 * sK1W[384 + k0] + e4 * sK1W[512 + k0] + e5 * sK1W[640 + k0];
            float v1 = sK1B[k0 + 1] + e0 * sK1W[k0 + 1] + e1 * sK1W[128 + k0 + 1]
                     + e2 * sK1W[256 + k0 + 1] + e3 * sK1W[384 + k0 + 1]
                     + e4 * sK1W[512 + k0 + 1] + e5 * sK1W[640 + k0 + 1];
            *(__half2*)(d + r * GK_SAS + cp2 * 2) =
                __floats2half2_rn(fmaxf(v0, 0.f), fmaxf(v1, 0.f));
        }
    };
    auto loadB = [&](int kt, int buf) {
#pragma unroll
        for (int i = 0; i < (64 * (BN / 8)) / NTHR; ++i) {
            int idx = i * NTHR + tid;
            int r = idx / (BN / 8), q = idx % (BN / 8);
            cp_async16g(sB + buf * 64 * SBS + r * SBS + q * 8,
                        B + (size_t)(kt * 64 + r) * N + n0 + q * 8);
        }
    };

    float acc[4][NT][4];
#pragma unroll
    for (int mt = 0; mt < 4; ++mt)
#pragma unroll
        for (int nt = 0; nt < NT; ++nt)
#pragma unroll
            for (int r = 0; r < 4; ++r) acc[mt][nt][r] = 0.f;

    const int KT = K / 64;

    if (FUSE_A) computeA(0, 0); else loadA(0, 0);
    loadB(0, 0);
    cp_commit();

    for (int kt = 0; kt < KT; ++kt) {
        int buf = kt & 1;
        if (kt + 1 < KT) {
            if (FUSE_A) computeA(kt + 1, buf ^ 1); else loadA(kt + 1, buf ^ 1);
            loadB(kt + 1, buf ^ 1);
            cp_commit();
            cp_wait1();
        } else {
            cp_wait0();
        }
        __syncthreads();

        const __half* a_s = sA + buf * 128 * GK_SAS;
        const __half* b_s = sB + buf * 64 * SBS;

#pragma unroll
        for (int ks = 0; ks < 4; ++ks) {
            uint32_t afrag[4][4], bfrag[NT][2];
#pragma unroll
            for (int mt = 0; mt < 4; ++mt) {
                int row = wm + mt * 16 + (lane & 15);
                int col = ks * 16 + (lane >> 4) * 8;
                ldmatrix_x4(afrag[mt], a_s + row * GK_SAS + col);
            }
#pragma unroll
            for (int nt = 0; nt < NT; ++nt) {
                int krow = ks * 16 + (lane & 15);
                ldmatrix_x2_trans(bfrag[nt], b_s + krow * SBS + wn + nt * 8);
            }
#pragma unroll
            for (int mt = 0; mt < 4; ++mt)
#pragma unroll
                for (int nt = 0; nt < NT; ++nt)
                    mma_m16n8k16_f16(acc[mt][nt], afrag[mt], bfrag[nt]);
        }
        __syncthreads();
    }

    // epilogue: bias (+ optional relu), fp16 output
#pragma unroll
    for (int mt = 0; mt < 4; ++mt) {
        int r0 = m0 + wm + mt * 16 + (lane >> 2);
#pragma unroll
        for (int nt = 0; nt < NT; ++nt) {
            int c0 = n0 + wn + nt * 8 + (lane & 3) * 2;
            float bv0 = bias[c0], bv1 = bias[c0 + 1];
            if (r0 < M) {
                float v0 = acc[mt][nt][0] + bv0;
                float v1 = acc[mt][nt][1] + bv1;
                if (RELU) { v0 = fmaxf(v0, 0.f); v1 = fmaxf(v1, 0.f); }
                *(__half2*)(C + (size_t)r0 * N + c0) = __floats2half2_rn(v0, v1);
            }
            if (r0 + 8 < M) {
                float v2 = acc[mt][nt][2] + bv0;
                float v3 = acc[mt][nt][3] + bv1;
                if (RELU) { v2 = fmaxf(v2, 0.f); v3 = fmaxf(v3, 0.f); }
                *(__half2*)(C + (size_t)(r0 + 8) * N + c0) = __floats2half2_rn(v2, v3);
            }
        }
    }
}

// k2 fused: BN=128 (WN_=8, NT=2), 512 thr. k3: BN=256 (WN_=8, NT=4), 512 thr.
#define SMEM_K2 ((2 * 128 * GK_SAS + 2 * 64 * (128 + 8)) * 2 + 1664 * 4)
#define SMEM_K3 ((2 * 128 * GK_SAS + 2 * 64 * (256 + 8)) * 2)

// ---------------- elementwise / small kernels ----------------
__global__ void zero_kernel(float* p, int n) {
    int i = blockIdx.x * blockDim.x + threadIdx.x;
    if (i < n) p[i] = 0.f;
}

// fp32 -> fp16 weight pre-conversion (both kept [K,N] row-major)
__global__ void convert_w_kernel(const float* __restrict__ k2w, const float* __restrict__ k3w,
                                 __half* __restrict__ w2h, __half* __restrict__ w3h) {
    int i = blockIdx.x * blockDim.x + threadIdx.x;
    if (i < 32768) w2h[i] = __float2half_rn(k2w[i]);
    if (i < 262144) w3h[i] = __float2half_rn(k3w[i]);
}

__global__ void count_deg_kernel(const int* __restrict__ dst, float* __restrict__ cnt, int E) {
    int e = blockIdx.x * blockDim.x + threadIdx.x;
    if (e < E) atomicAdd(&cnt[dst[e]], 1.0f);
}

// h0 = x @ fc1_w + fc1_b
__global__ void node_init_kernel(const float* __restrict__ x, const float* __restrict__ w,
                                 const float* __restrict__ b, float* __restrict__ h, int Nn) {
    int i = blockIdx.x * blockDim.x + threadIdx.x;
    if (i >= Nn * 32) return;
    int n = i >> 5, o = i & 31;
    float acc = b[o];
#pragma unroll
    for (int k = 0; k < 6; ++k) acc += x[n * 6 + k] * w[k * 32 + o];
    h[i] = acc;
}

// one warp per edge: msg = h[src] @ W_e (32x32 fp16), atomic scatter into aggr[dst]
__global__ void __launch_bounds__(256)
scatter_kernel(const float* __restrict__ h, const __half* __restrict__ we,
               const int* __restrict__ src, const int* __restrict__ dst,
               float* __restrict__ aggr, int E) {
    int e = blockIdx.x * 8 + (threadIdx.x >> 5);
    if (e >= E) return;
    int lane = threadIdx.x & 31;
    int s = src[e];
    int d = dst[e];
    float hv = h[s * 32 + lane];
    const __half2* W2 = (const __half2*)(we + (size_t)e * 1024);
    int r = lane >> 4;
    int oc = lane & 15;
    float msg0 = 0.f, msg1 = 0.f;
#pragma unroll
    for (int i = 0; i < 32; i += 2) {
        __half2 wv = W2[(i + r) * 16 + oc];
        float2 wf = __half22float2(wv);
        float hi = __shfl_sync(0xffffffffu, hv, i + r);
        msg0 += hi * wf.x;
        msg1 += hi * wf.y;
    }
    msg0 += __shfl_xor_sync(0xffffffffu, msg0, 16);
    msg1 += __shfl_xor_sync(0xffffffffu, msg1, 16);
    if (lane < 16) {
        atomicAdd(&aggr[d * 32 + 2 * oc], msg0);
        atomicAdd(&aggr[d * 32 + 2 * oc + 1], msg1);
    }
}

// h = aggr/denom + h @ root_w + conv_b (+ relu except last); zeroes aggr for next depth
__global__ void __launch_bounds__(256)
update_kernel(float* __restrict__ aggr, const float* __restrict__ cnt,
              const float* __restrict__ rootw, const float* __restrict__ bias,
              float* __restrict__ h, int Nn, int do_relu) {
    int n = blockIdx.x * 8 + (threadIdx.x >> 5);
    if (n >= Nn) return;
    int lane = threadIdx.x & 31;
    float hv = h[n * 32 + lane];
    float r = 0.f;
#pragma unroll
    for (int i = 0; i < 32; ++i) {
        float hi = __shfl_sync(0xffffffffu, hv, i);
        r += hi * rootw[i * 32 + lane];
    }
    float den = fmaxf(cnt[n], 1.0f);
    float a = aggr[n * 32 + lane];
    aggr[n * 32 + lane] = 0.f;
    float v = a / den + r + bias[lane];
    if (do_relu) v = fmaxf(v, 0.f);
    h[n * 32 + lane] = v;
}

// out[n] = relu(h @ fc2 + b2) @ fc3 + b3
__global__ void __launch_bounds__(256)
readout_kernel(const float* __restrict__ h, const float* __restrict__ w2,
               const float* __restrict__ b2, const float* __restrict__ w3,
               const float* __restrict__ b3, float* __restrict__ out, int Nn) {
    int n = blockIdx.x * 8 + (threadIdx.x >> 5);
    if (n >= Nn) return;
    int lane = threadIdx.x & 31;
    float hv = h[n * 32 + lane];
    float acc = 0.f;
#pragma unroll
    for (int jt = 0; jt < 4; ++jt) {
        int j = jt * 32 + lane;
        float y = b2[j];
#pragma unroll
        for (int i = 0; i < 32; ++i) {
            float hi = __shfl_sync(0xffffffffu, hv, i);
            y += hi * w2[i * 128 + j];
        }
        y = fmaxf(y, 0.f);
        acc += y * w3[j];
    }
#pragma unroll
    for (int off = 16; off; off >>= 1) acc += __shfl_down_sync(0xffffffffu, acc, off);
    if (lane == 0) out[n] = acc + b3[0];
}

// ---------------- launch ----------------
extern "C" void kernel_launch(void* const* d_in, const int* in_sizes, int n_in,
                              void* d_out, int out_size) {
    const float* x     = (const float*)d_in[0];
    const int*   ei    = (const int*)d_in[1];
    const float* ea    = (const float*)d_in[2];
    const float* fc1w  = (const float*)d_in[3];
    const float* fc1b  = (const float*)d_in[4];
    const float* k1w   = (const float*)d_in[5];
    const float* k1b   = (const float*)d_in[6];
    const float* k2w   = (const float*)d_in[7];
    const float* k2b   = (const float*)d_in[8];
    const float* k3w   = (const float*)d_in[9];
    const float* k3b   = (const float*)d_in[10];
    const float* rootw = (const float*)d_in[11];
    const float* convb = (const float*)d_in[12];
    const float* fc2w  = (const float*)d_in[13];
    const float* fc2b  = (const float*)d_in[14];
    const float* fc3w  = (const float*)d_in[15];
    const float* fc3b  = (const float*)d_in[16];
    float* out = (float*)d_out;

    const int Nn = in_sizes[0] / 6;        // 10000
    const int E  = in_sizes[2] / 6;        // 120000
    const int* src = ei;
    const int* dst = ei + E;

    float *p_h, *p_aggr, *p_cnt;
    __half *p_h2, *p_we, *p_w2h, *p_w3h;
    cudaGetSymbolAddress((void**)&p_h2, g_h2);
    cudaGetSymbolAddress((void**)&p_we, g_we);
    cudaGetSymbolAddress((void**)&p_w2h, g_w2h);
    cudaGetSymbolAddress((void**)&p_w3h, g_w3h);
    cudaGetSymbolAddress((void**)&p_h, g_h);
    cudaGetSymbolAddress((void**)&p_aggr, g_aggr);
    cudaGetSymbolAddress((void**)&p_cnt, g_cnt);

    cudaFuncSetAttribute((const void*)gemm_f16_kernel<true, true, 8, 2>,
                         cudaFuncAttributeMaxDynamicSharedMemorySize, SMEM_K2);
    cudaFuncSetAttribute((const void*)gemm_f16_kernel<false, false, 8, 4>,
                         cudaFuncAttributeMaxDynamicSharedMemorySize, SMEM_K3);

    // edge MLP: convert weights, then fused (l1+k2) GEMM, then k3 GEMM
    convert_w_kernel<<<(262144 + 255) / 256, 256>>>(k2w, k3w, p_w2h, p_w3h);
    {
        dim3 grid2(2, (E + 127) / 128);
        gemm_f16_kernel<true, true, 8, 2><<<grid2, 512, SMEM_K2>>>(
            nullptr, ea, k1w, k1b, p_w2h, k2b, p_h2, E, 256, 128);
        dim3 grid3(4, (E + 127) / 128);
        gemm_f16_kernel<false, false, 8, 4><<<grid3, 512, SMEM_K3>>>(
            p_h2, nullptr, nullptr, nullptr, p_w3h, k3b, p_we, E, 1024, 256);
    }

    // node embedding + degree + aggr init
    node_init_kernel<<<(Nn * 32 + 255) / 256, 256>>>(x, fc1w, fc1b, p_h, Nn);
    zero_kernel<<<(Nn + 255) / 256, 256>>>(p_cnt, Nn);
    count_deg_kernel<<<(E + 255) / 256, 256>>>(dst, p_cnt, E);
    zero_kernel<<<(Nn * 32 + 255) / 256, 256>>>(p_aggr, Nn * 32);

    // 4 rounds of NNConv message passing
    for (int d = 0; d < 4; ++d) {
        scatter_kernel<<<(E + 7) / 8, 256>>>(p_h, p_we, src, dst, p_aggr, E);
        update_kernel<<<(Nn + 7) / 8, 256>>>(p_aggr, p_cnt, rootw, convb, p_h, Nn,
                                             (d < 3) ? 1 : 0);
    }

    // readout
    readout_kernel<<<(Nn + 7) / 8, 256>>>(p_h, fc2w, fc2b, fc3w, fc3b, out, Nn);
}

// round 11
// speedup vs baseline: 1.4921x; 1.4921x over previous
#include <cuda_runtime.h>
#include <cuda_fp16.h>
#include <cstdint>

// Problem constants (fixed by the dataset)
#define NN_MAX 10000
#define EE_MAX 120000

// ---------------- scratch (device globals; no allocation allowed) ----------------
__device__ __half g_h1[(size_t)EE_MAX * 128];         // 30.7 MB (fp16)
__device__ __half g_h2[(size_t)EE_MAX * 256];         // 61.4 MB (fp16)
__device__ __half g_we[(size_t)EE_MAX * 1024];        // 245.8 MB (fp16)
__device__ __half g_w2h[128 * 256];                   // k2_w fp16 [K,N]
__device__ __half g_w3h[256 * 1024];                  // k3_w fp16 [K,N]
__device__ float g_h[(size_t)NN_MAX * 32];
__device__ float g_aggr[(size_t)NN_MAX * 32];
__device__ float g_cnt[(size_t)NN_MAX];

// ---------------- mma / ldmatrix / cp.async helpers ----------------
__device__ __forceinline__ void mma_m16n8k16_f16(float* c, const uint32_t* a, const uint32_t* b) {
    asm volatile(
        "mma.sync.aligned.m16n8k16.row.col.f32.f16.f16.f32 "
        "{%0,%1,%2,%3}, {%4,%5,%6,%7}, {%8,%9}, {%0,%1,%2,%3};\n"
        : "+f"(c[0]), "+f"(c[1]), "+f"(c[2]), "+f"(c[3])
        : "r"(a[0]), "r"(a[1]), "r"(a[2]), "r"(a[3]), "r"(b[0]), "r"(b[1]));
}

__device__ __forceinline__ void ldmatrix_x4(uint32_t* r, const __half* smem_ptr) {
    uint32_t addr = (uint32_t)__cvta_generic_to_shared(smem_ptr);
    asm volatile("ldmatrix.sync.aligned.m8n8.x4.shared.b16 {%0,%1,%2,%3}, [%4];"
                 : "=r"(r[0]), "=r"(r[1]), "=r"(r[2]), "=r"(r[3]) : "r"(addr));
}

__device__ __forceinline__ void ldmatrix_x2_trans(uint32_t* r, const __half* smem_ptr) {
    uint32_t addr = (uint32_t)__cvta_generic_to_shared(smem_ptr);
    asm volatile("ldmatrix.sync.aligned.m8n8.x2.trans.shared.b16 {%0,%1}, [%2];"
                 : "=r"(r[0]), "=r"(r[1]) : "r"(addr));
}

__device__ __forceinline__ void cp_async16g(__half* smem_dst, const __half* gmem_src) {
    uint32_t s = (uint32_t)__cvta_generic_to_shared(smem_dst);
    asm volatile("cp.async.cg.shared.global [%0], [%1], 16;\n" :: "r"(s), "l"(gmem_src));
}
__device__ __forceinline__ void cp_async16p(__half* smem_dst, const __half* gmem_src, int src_bytes) {
    uint32_t s = (uint32_t)__cvta_generic_to_shared(smem_dst);
    asm volatile("cp.async.cg.shared.global [%0], [%1], 16, %2;\n"
                 :: "r"(s), "l"(gmem_src), "r"(src_bytes));
}
__device__ __forceinline__ void cp_commit() { asm volatile("cp.async.commit_group;\n"); }
__device__ __forceinline__ void cp_wait1() { asm volatile("cp.async.wait_group 1;\n"); }
__device__ __forceinline__ void cp_wait0() { asm volatile("cp.async.wait_group 0;\n"); }

// ---------------- fp16 GEMM, BK=32, BN=128, 3-stage cp.async, 1 barrier/iter ----------
// C[M,N] = op(A[M,K] @ B[K,N] + bias). A,B,C fp16, bias fp32.
// 256 threads, warps 2(m) x 4(n), warp tile 64x32, occ 2.
#define G_SAS 40                      // halves per A row (32 + 8 pad)
#define G_SBS 136                     // halves per B row (128 + 8 pad)
#define G_BUF_A (128 * G_SAS)
#define G_BUF_B (32 * G_SBS)
#define GEMM_SMEM (3 * (G_BUF_A + G_BUF_B) * 2)

template <bool RELU>
__global__ void __launch_bounds__(256, 2)
gemm_f16_3s(const __half* __restrict__ A, const __half* __restrict__ B,
            const float* __restrict__ bias, __half* __restrict__ C,
            int M, int N, int K) {
    extern __shared__ __half sm[];
    __half* sA = sm;                        // [3][128][G_SAS]
    __half* sB = sm + 3 * G_BUF_A;          // [3][32][G_SBS]

    const int tid = threadIdx.x;
    const int warp = tid >> 5;
    const int lane = tid & 31;
    const int wm = (warp >> 2) * 64;
    const int wn = (warp & 3) * 32;
    const int m0 = blockIdx.y * 128;
    const int n0 = blockIdx.x * 128;

    auto loadA = [&](int kt, int s) {
#pragma unroll
        for (int i = 0; i < 2; ++i) {
            int idx = i * 256 + tid;
            int r = idx >> 2, seg = idx & 3;
            int gr = m0 + r;
            int grc = gr < M ? gr : (M - 1);
            cp_async16p(sA + s * G_BUF_A + r * G_SAS + seg * 8,
                        A + (size_t)grc * K + kt * 32 + seg * 8, gr < M ? 16 : 0);
        }
    };
    auto loadB = [&](int kt, int s) {
#pragma unroll
        for (int i = 0; i < 2; ++i) {
            int idx = i * 256 + tid;
            int r = idx >> 4, q = idx & 15;
            cp_async16g(sB + s * G_BUF_B + r * G_SBS + q * 8,
                        B + (size_t)(kt * 32 + r) * N + n0 + q * 8);
        }
    };

    float acc[4][4][4];
#pragma unroll
    for (int mt = 0; mt < 4; ++mt)
#pragma unroll
        for (int nt = 0; nt < 4; ++nt)
#pragma unroll
            for (int r = 0; r < 4; ++r) acc[mt][nt][r] = 0.f;

    const int KT = K / 32;

    loadA(0, 0); loadB(0, 0); cp_commit();
    if (KT > 1) { loadA(1, 1); loadB(1, 1); cp_commit(); }

    for (int kt = 0; kt < KT; ++kt) {
        int s = kt % 3;
        if (kt + 1 < KT) cp_wait1(); else cp_wait0();   // stage kt resident (committed depth kt+2)
        __syncthreads();                                // visibility + frees buffer (kt+2)%3
        if (kt + 2 < KT) {                              // prefetch 2 ahead
            loadA(kt + 2, (kt + 2) % 3);
            loadB(kt + 2, (kt + 2) % 3);
            cp_commit();
        }

        const __half* a_s = sA + s * G_BUF_A;
        const __half* b_s = sB + s * G_BUF_B;
#pragma unroll
        for (int ks = 0; ks < 2; ++ks) {
            uint32_t afrag[4][4], bfrag[4][2];
#pragma unroll
            for (int mt = 0; mt < 4; ++mt) {
                int row = wm + mt * 16 + (lane & 15);
                int col = ks * 16 + (lane >> 4) * 8;
                ldmatrix_x4(afrag[mt], a_s + row * G_SAS + col);
            }
#pragma unroll
            for (int nt = 0; nt < 4; ++nt) {
                int krow = ks * 16 + (lane & 15);
                ldmatrix_x2_trans(bfrag[nt], b_s + krow * G_SBS + wn + nt * 8);
            }
#pragma unroll
            for (int mt = 0; mt < 4; ++mt)
#pragma unroll
                for (int nt = 0; nt < 4; ++nt)
                    mma_m16n8k16_f16(acc[mt][nt], afrag[mt], bfrag[nt]);
        }
    }

    // epilogue: bias (+ optional relu), fp16 output
#pragma unroll
    for (int mt = 0; mt < 4; ++mt) {
        int r0 = m0 + wm + mt * 16 + (lane >> 2);
#pragma unroll
        for (int nt = 0; nt < 4; ++nt) {
            int c0 = n0 + wn + nt * 8 + (lane & 3) * 2;
            float bv0 = bias[c0], bv1 = bias[c0 + 1];
            if (r0 < M) {
                float v0 = acc[mt][nt][0] + bv0;
                float v1 = acc[mt][nt][1] + bv1;
                if (RELU) { v0 = fmaxf(v0, 0.f); v1 = fmaxf(v1, 0.f); }
                *(__half2*)(C + (size_t)r0 * N + c0) = __floats2half2_rn(v0, v1);
            }
            if (r0 + 8 < M) {
                float v2 = acc[mt][nt][2] + bv0;
                float v3 = acc[mt][nt][3] + bv1;
                if (RELU) { v2 = fmaxf(v2, 0.f); v3 = fmaxf(v3, 0.f); }
                *(__half2*)(C + (size_t)(r0 + 8) * N + c0) = __floats2half2_rn(v2, v3);
            }
        }
    }
}

// ---------------- elementwise / small kernels ----------------
__global__ void zero_kernel(float* p, int n) {
    int i = blockIdx.x * blockDim.x + threadIdx.x;
    if (i < n) p[i] = 0.f;
}

// fp32 -> fp16 weight pre-conversion
__global__ void convert_w_kernel(const float* __restrict__ k2w, const float* __restrict__ k3w,
                                 __half* __restrict__ w2h, __half* __restrict__ w3h) {
    int i = blockIdx.x * blockDim.x + threadIdx.x;
    if (i < 32768) w2h[i] = __float2half_rn(k2w[i]);
    if (i < 262144) w3h[i] = __float2half_rn(k3w[i]);
}

__global__ void count_deg_kernel(const int* __restrict__ dst, float* __restrict__ cnt, int E) {
    int e = blockIdx.x * blockDim.x + threadIdx.x;
    if (e < E) atomicAdd(&cnt[dst[e]], 1.0f);
}

// h0 = x @ fc1_w + fc1_b
__global__ void node_init_kernel(const float* __restrict__ x, const float* __restrict__ w,
                                 const float* __restrict__ b, float* __restrict__ h, int Nn) {
    int i = blockIdx.x * blockDim.x + threadIdx.x;
    if (i >= Nn * 32) return;
    int n = i >> 5, o = i & 31;
    float acc = b[o];
#pragma unroll
    for (int k = 0; k < 6; ++k) acc += x[n * 6 + k] * w[k * 32 + o];
    h[i] = acc;
}

// h1 = relu(edge_attr @ k1_w + k1_b), fp16 out; one thread -> 4 outputs
__global__ void __launch_bounds__(256)
edge_l1_kernel(const float* __restrict__ ea, const float* __restrict__ w,
               const float* __restrict__ b, __half* __restrict__ h1, int E) {
    int t = blockIdx.x * blockDim.x + threadIdx.x;
    if (t >= E * 32) return;
    int e = t >> 5, q = t & 31;
    float a0 = ea[e * 6 + 0], a1 = ea[e * 6 + 1], a2 = ea[e * 6 + 2];
    float a3 = ea[e * 6 + 3], a4 = ea[e * 6 + 4], a5 = ea[e * 6 + 5];
    const float4* w4 = (const float4*)w;
    const float4* b4 = (const float4*)b;
    float4 acc = b4[q];
    float4 r0 = w4[0 * 32 + q], r1 = w4[1 * 32 + q], r2 = w4[2 * 32 + q];
    float4 r3 = w4[3 * 32 + q], r4 = w4[4 * 32 + q], r5 = w4[5 * 32 + q];
    acc.x += a0 * r0.x + a1 * r1.x + a2 * r2.x + a3 * r3.x + a4 * r4.x + a5 * r5.x;
    acc.y += a0 * r0.y + a1 * r1.y + a2 * r2.y + a3 * r3.y + a4 * r4.y + a5 * r5.y;
    acc.z += a0 * r0.z + a1 * r1.z + a2 * r2.z + a3 * r3.z + a4 * r4.z + a5 * r5.z;
    acc.w += a0 * r0.w + a1 * r1.w + a2 * r2.w + a3 * r3.w + a4 * r4.w + a5 * r5.w;
    __half2 lo = __floats2half2_rn(fmaxf(acc.x, 0.f), fmaxf(acc.y, 0.f));
    __half2 hi = __floats2half2_rn(fmaxf(acc.z, 0.f), fmaxf(acc.w, 0.f));
    __half2* out = (__half2*)(h1 + (size_t)e * 128 + q * 4);
    out[0] = lo;
    out[1] = hi;
}

// one warp per edge: msg = h[src] @ W_e (32x32 fp16), atomic scatter into aggr[dst]
__global__ void __launch_bounds__(256)
scatter_kernel(const float* __restrict__ h, const __half* __restrict__ we,
               const int* __restrict__ src, const int* __restrict__ dst,
               float* __restrict__ aggr, int E) {
    int e = blockIdx.x * 8 + (threadIdx.x >> 5);
    if (e >= E) return;
    int lane = threadIdx.x & 31;
    int s = src[e];
    int d = dst[e];
    float hv = h[s * 32 + lane];
    const __half2* W2 = (const __half2*)(we + (size_t)e * 1024);
    int r = lane >> 4;
    int oc = lane & 15;
    float msg0 = 0.f, msg1 = 0.f;
#pragma unroll
    for (int i = 0; i < 32; i += 2) {
        __half2 wv = W2[(i + r) * 16 + oc];
        float2 wf = __half22float2(wv);
        float hi = __shfl_sync(0xffffffffu, hv, i + r);
        msg0 += hi * wf.x;
        msg1 += hi * wf.y;
    }
    msg0 += __shfl_xor_sync(0xffffffffu, msg0, 16);
    msg1 += __shfl_xor_sync(0xffffffffu, msg1, 16);
    if (lane < 16) {
        atomicAdd(&aggr[d * 32 + 2 * oc], msg0);
        atomicAdd(&aggr[d * 32 + 2 * oc + 1], msg1);
    }
}

// h = aggr/denom + h @ root_w + conv_b (+ relu except last); zeroes aggr for next depth
__global__ void __launch_bounds__(256)
update_kernel(float* __restrict__ aggr, const float* __restrict__ cnt,
              const float* __restrict__ rootw, const float* __restrict__ bias,
              float* __restrict__ h, int Nn, int do_relu) {
    int n = blockIdx.x * 8 + (threadIdx.x >> 5);
    if (n >= Nn) return;
    int lane = threadIdx.x & 31;
    float hv = h[n * 32 + lane];
    float r = 0.f;
#pragma unroll
    for (int i = 0; i < 32; ++i) {
        float hi = __shfl_sync(0xffffffffu, hv, i);
        r += hi * rootw[i * 32 + lane];
    }
    float den = fmaxf(cnt[n], 1.0f);
    float a = aggr[n * 32 + lane];
    aggr[n * 32 + lane] = 0.f;
    float v = a / den + r + bias[lane];
    if (do_relu) v = fmaxf(v, 0.f);
    h[n * 32 + lane] = v;
}

// out[n] = relu(h @ fc2 + b2) @ fc3 + b3
__global__ void __launch_bounds__(256)
readout_kernel(const float* __restrict__ h, const float* __restrict__ w2,
               const float* __restrict__ b2, const float* __restrict__ w3,
               const float* __restrict__ b3, float* __restrict__ out, int Nn) {
    int n = blockIdx.x * 8 + (threadIdx.x >> 5);
    if (n >= Nn) return;
    int lane = threadIdx.x & 31;
    float hv = h[n * 32 + lane];
    float acc = 0.f;
#pragma unroll
    for (int jt = 0; jt < 4; ++jt) {
        int j = jt * 32 + lane;
        float y = b2[j];
#pragma unroll
        for (int i = 0; i < 32; ++i) {
            float hi = __shfl_sync(0xffffffffu, hv, i);
            y += hi * w2[i * 128 + j];
        }
        y = fmaxf(y, 0.f);
        acc += y * w3[j];
    }
#pragma unroll
    for (int off = 16; off; off >>= 1) acc += __shfl_down_sync(0xffffffffu, acc, off);
    if (lane == 0) out[n] = acc + b3[0];
}

// ---------------- launch ----------------
extern "C" void kernel_launch(void* const* d_in, const int* in_sizes, int n_in,
                              void* d_out, int out_size) {
    const float* x     = (const float*)d_in[0];
    const int*   ei    = (const int*)d_in[1];
    const float* ea    = (const float*)d_in[2];
    const float* fc1w  = (const float*)d_in[3];
    const float* fc1b  = (const float*)d_in[4];
    const float* k1w   = (const float*)d_in[5];
    const float* k1b   = (const float*)d_in[6];
    const float* k2w   = (const float*)d_in[7];
    const float* k2b   = (const float*)d_in[8];
    const float* k3w   = (const float*)d_in[9];
    const float* k3b   = (const float*)d_in[10];
    const float* rootw = (const float*)d_in[11];
    const float* convb = (const float*)d_in[12];
    const float* fc2w  = (const float*)d_in[13];
    const float* fc2b  = (const float*)d_in[14];
    const float* fc3w  = (const float*)d_in[15];
    const float* fc3b  = (const float*)d_in[16];
    float* out = (float*)d_out;

    const int Nn = in_sizes[0] / 6;        // 10000
    const int E  = in_sizes[2] / 6;        // 120000
    const int* src = ei;
    const int* dst = ei + E;

    float *p_h, *p_aggr, *p_cnt;
    __half *p_h1, *p_h2, *p_we, *p_w2h, *p_w3h;
    cudaGetSymbolAddress((void**)&p_h1, g_h1);
    cudaGetSymbolAddress((void**)&p_h2, g_h2);
    cudaGetSymbolAddress((void**)&p_we, g_we);
    cudaGetSymbolAddress((void**)&p_w2h, g_w2h);
    cudaGetSymbolAddress((void**)&p_w3h, g_w3h);
    cudaGetSymbolAddress((void**)&p_h, g_h);
    cudaGetSymbolAddress((void**)&p_aggr, g_aggr);
    cudaGetSymbolAddress((void**)&p_cnt, g_cnt);

    cudaFuncSetAttribute((const void*)gemm_f16_3s<true>,
                         cudaFuncAttributeMaxDynamicSharedMemorySize, GEMM_SMEM);
    cudaFuncSetAttribute((const void*)gemm_f16_3s<false>,
                         cudaFuncAttributeMaxDynamicSharedMemorySize, GEMM_SMEM);

    // edge MLP: convert weights, l1, k2, k3 (k3 at the ncu capture slot)
    convert_w_kernel<<<(262144 + 255) / 256, 256>>>(k2w, k3w, p_w2h, p_w3h);
    edge_l1_kernel<<<(E * 32 + 255) / 256, 256>>>(ea, k1w, k1b, p_h1, E);
    {
        dim3 grid2(2, (E + 127) / 128);
        gemm_f16_3s<true><<<grid2, 256, GEMM_SMEM>>>(p_h1, p_w2h, k2b, p_h2, E, 256, 128);
        dim3 grid3(8, (E + 127) / 128);
        gemm_f16_3s<false><<<grid3, 256, GEMM_SMEM>>>(p_h2, p_w3h, k3b, p_we, E, 1024, 256);
    }

    // node embedding + degree + aggr init
    node_init_kernel<<<(Nn * 32 + 255) / 256, 256>>>(x, fc1w, fc1b, p_h, Nn);
    zero_kernel<<<(Nn + 255) / 256, 256>>>(p_cnt, Nn);
    count_deg_kernel<<<(E + 255) / 256, 256>>>(dst, p_cnt, E);
    zero_kernel<<<(Nn * 32 + 255) / 256, 256>>>(p_aggr, Nn * 32);

    // 4 rounds of NNConv message passing
    for (int d = 0; d < 4; ++d) {
        scatter_kernel<<<(E + 7) / 8, 256>>>(p_h, p_we, src, dst, p_aggr, E);
        update_kernel<<<(Nn + 7) / 8, 256>>>(p_aggr, p_cnt, rootw, convb, p_h, Nn,
                                             (d < 3) ? 1 : 0);
    }

    // readout
    readout_kernel<<<(Nn + 7) / 8, 256>>>(p_h, fc2w, fc2b, fc3w, fc3b, out, Nn);
}